// round 10
// baseline (speedup 1.0000x reference)
#include <cuda_runtime.h>
#include <math.h>
#include <stdint.h>

#define R_ROIS   128
#define C_CH     512
#define HW       32
#define ROI      7
#define FLATK    25088      // 512*7*7
#define HID      4096
#define NLOC     84
#define NSCORE   21
#define SPLITS6  9
#define SPLITS7  8
#define HOUT     105        // 84 + 21
#define HSPLITS  128        // heads split-K count (K32 each)

// -------- scratch (static device globals; no runtime allocation) --------
__device__ float g_flat[R_ROIS * FLATK];            // tf32-valued
__device__ float g_fc6 [R_ROIS * HID];              // tf32-valued
__device__ float g_fc7 [R_ROIS * HID];              // fp32
__device__ float g_part[SPLITS6 * R_ROIS * HID];

// ============================ helpers ============================
__device__ __forceinline__ uint32_t smem_u32(const void* p) {
    uint32_t a;
    asm("{ .reg .u64 t; cvta.to.shared.u64 t, %1; cvt.u32.u64 %0, t; }" : "=r"(a) : "l"(p));
    return a;
}
__device__ __forceinline__ uint32_t f2tf32(float x) {
    uint32_t r; asm("cvt.rna.tf32.f32 %0, %1;" : "=r"(r) : "f"(x)); return r;
}
__device__ __forceinline__ void bulk_cp(uint32_t dst, const void* src, uint32_t bytes, uint32_t mbar) {
    asm volatile("cp.async.bulk.shared::cta.global.mbarrier::complete_tx::bytes [%0], [%1], %2, [%3];"
        :: "r"(dst), "l"(src), "r"(bytes), "r"(mbar) : "memory");
}
#define MBAR_INIT(mb, c)  asm volatile("mbarrier.init.shared.b64 [%0], %1;" :: "r"(mb), "r"((uint32_t)(c)) : "memory")
#define MBAR_EXPECT(mb, b) asm volatile("mbarrier.arrive.expect_tx.shared.b64 _, [%0], %1;" :: "r"(mb), "r"((uint32_t)(b)) : "memory")
#define MBAR_WAIT(mb, ph) do {                                                  \
    uint32_t _m = (mb), _p = (ph), _d;                                          \
    asm volatile("{ .reg .pred p; mbarrier.try_wait.parity.acquire.cta.shared::cta.b64 p, [%1], %2; selp.b32 %0, 1, 0, p; }" \
        : "=r"(_d) : "r"(_m), "r"(_p) : "memory");                              \
    if (!_d) {                                                                  \
        asm volatile("{ .reg .pred P1; WL_%=: mbarrier.try_wait.parity.acquire.cta.shared::cta.b64 P1, [%0], %1, 0x989680; @P1 bra.uni WD_%=; bra.uni WL_%=; WD_%=: }" \
            :: "r"(_m), "r"(_p) : "memory");                                    \
    }                                                                           \
} while (0)

__device__ __forceinline__ void mma8(float* d,
                                     uint32_t a0, uint32_t a1, uint32_t a2, uint32_t a3,
                                     uint32_t b0, uint32_t b1) {
    asm volatile(
        "mma.sync.aligned.m16n8k8.row.col.f32.tf32.tf32.f32 "
        "{%0,%1,%2,%3}, {%4,%5,%6,%7}, {%8,%9}, {%0,%1,%2,%3};"
        : "+f"(d[0]), "+f"(d[1]), "+f"(d[2]), "+f"(d[3])
        : "r"(a0), "r"(a1), "r"(a2), "r"(a3), "r"(b0), "r"(b1));
}

// SMEM geometry (bytes). K64 stages, raw k-major, conflict-free pitches.
//  A: 128 rows x 76 floats pitch (304 B/row), tf32-valued, via bulk DMA
//  B: 64 k-rows x 264 floats pitch (1056 B/row), raw fp32, via bulk DMA
#define PA          76
#define PB          264
#define A_BYTES     (128 * PA * 4)          // 38912
#define B_OFFB      A_BYTES
#define STAGE_BYTES (A_BYTES + 64 * PB * 4) // 106496
#define SMEM_TOT    (128 + 2 * STAGE_BYTES) // 213120
#define STAGE_TX    (128 * 256 + 64 * 1024) // 98304

// ============================ RoI max pool (writes tf32-valued) ============================
__global__ void roi_pool_kernel(const float* __restrict__ x,
                                const float* __restrict__ rois,
                                const int*   __restrict__ roi_idx) {
    int i = blockIdx.x * blockDim.x + threadIdx.x;
    if (i >= R_ROIS * FLATK) return;
    int pw = i % ROI;
    int ph = (i / ROI) % ROI;
    int c  = (i / (ROI * ROI)) % C_CH;
    int r  = i / FLATK;

    float y1 = rois[r * 4 + 0];
    float x1 = rois[r * 4 + 1];
    float y2 = rois[r * 4 + 2];
    float x2 = rois[r * 4 + 3];

    float sw = rintf(x1 * 0.0625f);
    float sh = rintf(y1 * 0.0625f);
    float ew = rintf(x2 * 0.0625f);
    float eh = rintf(y2 * 0.0625f);
    float bin_w = fmaxf(ew - sw + 1.0f, 1.0f) * (1.0f / (float)ROI);
    float bin_h = fmaxf(eh - sh + 1.0f, 1.0f) * (1.0f / (float)ROI);

    int ws = (int)fminf(fmaxf(floorf((float)pw       * bin_w) + sw, 0.0f), 32.0f);
    int we = (int)fminf(fmaxf(ceilf ((float)(pw + 1) * bin_w) + sw, 0.0f), 32.0f);
    int hs = (int)fminf(fmaxf(floorf((float)ph       * bin_h) + sh, 0.0f), 32.0f);
    int he = (int)fminf(fmaxf(ceilf ((float)(ph + 1) * bin_h) + sh, 0.0f), 32.0f);

    int spanW = we - ws;
    float out = 0.0f;
    if (spanW > 0 && he > hs) {
        const float* f = x + ((size_t)roi_idx[r] * C_CH + c) * (HW * HW);
        float m = -3.402823466e38f;
        for (int h = hs; h < he; h++) {
            const float* row = f + h * HW + ws;
#pragma unroll
            for (int dw = 0; dw < 6; dw++)
                if (dw < spanW) m = fmaxf(m, row[dw]);
        }
        out = m;
    }
    g_flat[i] = __uint_as_float(f2tf32(out));   // A-side tf32 cvt done here
}

// ============================ tf32 mma.sync split-K GEMM ============================
// CTA tile M128 x N256 x K64; 256 threads = 8 warps 2(M) x 4(N); warp tile 64x64.
// A (tf32-valued) and B (raw fp32, cvt at frag load) both arrive via cp.async.bulk DMA.

__device__ __forceinline__ void bulk_fill(uint32_t stage, uint32_t mbar,
                                          const char* Abase, size_t ldaB,
                                          const char* Bbase, int lane) {
    if (lane == 0) MBAR_EXPECT(mbar, STAGE_TX);
    __syncwarp();
#pragma unroll
    for (int i = 0; i < 4; i++) {
        int r = lane + i * 32;
        bulk_cp(stage + (uint32_t)r * (PA * 4), Abase + (size_t)r * ldaB, 256, mbar);
    }
#pragma unroll
    for (int i = 0; i < 2; i++) {
        int k = lane + i * 32;
        bulk_cp(stage + B_OFFB + (uint32_t)k * (PB * 4), Bbase + (size_t)k * (HID * 4), 1024, mbar);
    }
}

__device__ __forceinline__ void compute_stage(const float* st, float acc[4][8][4],
                                              int m0, int nw, int g, int t) {
    const float* Ab = st;
    const float* Bb = st + A_BYTES / 4;
#pragma unroll
    for (int ks = 0; ks < 8; ks++) {
        uint32_t a0[4], a1[4], a2[4], a3[4];
#pragma unroll
        for (int mi = 0; mi < 4; mi++) {
            int row0 = m0 + mi * 16 + g;
            a0[mi] = __float_as_uint(Ab[row0 * PA + ks * 8 + t]);
            a2[mi] = __float_as_uint(Ab[row0 * PA + ks * 8 + t + 4]);
            a1[mi] = __float_as_uint(Ab[(row0 + 8) * PA + ks * 8 + t]);
            a3[mi] = __float_as_uint(Ab[(row0 + 8) * PA + ks * 8 + t + 4]);
        }
        const float* brow0 = Bb + (ks * 8 + t)     * PB + nw + g;
        const float* brow1 = Bb + (ks * 8 + t + 4) * PB + nw + g;
#pragma unroll
        for (int j = 0; j < 8; j++) {
            uint32_t b0 = f2tf32(brow0[j * 8]);
            uint32_t b1 = f2tf32(brow1[j * 8]);
#pragma unroll
            for (int mi = 0; mi < 4; mi++)
                mma8(acc[mi][j], a0[mi], a1[mi], a2[mi], a3[mi], b0, b1);
        }
    }
}

__global__ void __launch_bounds__(256, 1) gemm_tc_kernel(const float* __restrict__ Wm,
                                                         int which, int iters_per_split) {
    extern __shared__ float sm[];
    const float* A = which ? g_fc6 : g_flat;
    const size_t ldaB = (size_t)(which ? HID : FLATK) * 4;
    const int totIters = (which ? HID : FLATK) / 64;

    const int tid  = threadIdx.x;
    const int lane = tid & 31, wid = tid >> 5;
    const int g    = lane >> 2, t = lane & 3;
    const int m0   = (wid & 1) * 64;
    const int nw   = (wid >> 1) * 64;
    const int n0   = blockIdx.x * 256;
    const int it0  = blockIdx.y * iters_per_split;
    const int nIt  = min(iters_per_split, totIters - it0);

    const uint32_t sb = smem_u32(sm);
    const uint32_t mb[2] = {sb, sb + 8};
    const uint32_t stg[2] = {sb + 128, sb + 128 + STAGE_BYTES};

    if (tid == 0) { MBAR_INIT(mb[0], 1); MBAR_INIT(mb[1], 1); }
    __syncthreads();

    if (wid == 0) {
#pragma unroll
        for (int s = 0; s < 2; s++) {
            if (s < nIt) {
                int kb = (it0 + s) * 64;
                bulk_fill(stg[s], mb[s],
                          (const char*)A + (size_t)kb * 4,
                          ldaB,
                          (const char*)Wm + ((size_t)kb * HID + n0) * 4,
                          lane);
            }
        }
    }

    float acc[4][8][4];
#pragma unroll
    for (int mi = 0; mi < 4; mi++)
#pragma unroll
        for (int j = 0; j < 8; j++)
#pragma unroll
            for (int e = 0; e < 4; e++) acc[mi][j][e] = 0.0f;

    int ph0 = 0, ph1 = 0;
    for (int it = 0; it < nIt; it++) {
        int b = it & 1;
        if (b) { MBAR_WAIT(mb[1], ph1); ph1 ^= 1; }
        else   { MBAR_WAIT(mb[0], ph0); ph0 ^= 1; }

        compute_stage(sm + (b ? STAGE_BYTES / 4 + 32 : 32), acc, m0, nw, g, t);
        __syncthreads();

        if (wid == 0 && it + 2 < nIt) {
            int kb = (it0 + it + 2) * 64;
            bulk_fill(stg[b], mb[b],
                      (const char*)A + (size_t)kb * 4,
                      ldaB,
                      (const char*)Wm + ((size_t)kb * HID + n0) * 4,
                      lane);
        }
    }

    // epilogue -> split-K partials
    float* P = g_part + (size_t)blockIdx.y * (R_ROIS * HID);
#pragma unroll
    for (int mi = 0; mi < 4; mi++) {
        int row = m0 + mi * 16 + g;
#pragma unroll
        for (int j = 0; j < 8; j++) {
            int col = n0 + nw + j * 8 + t * 2;
            *(float2*)&P[(size_t)row * HID + col]       = make_float2(acc[mi][j][0], acc[mi][j][1]);
            *(float2*)&P[(size_t)(row + 8) * HID + col] = make_float2(acc[mi][j][2], acc[mi][j][3]);
        }
    }
}

// ============================ split-K reduce + bias + relu ============================
__global__ void reduce_fc6_kernel(const float* __restrict__ b1) {
    int i = blockIdx.x * blockDim.x + threadIdx.x;
    if (i >= R_ROIS * HID) return;
    float s = 0.0f;
#pragma unroll
    for (int q = 0; q < SPLITS6; q++) s += g_part[(size_t)q * R_ROIS * HID + i];
    s += b1[i & (HID - 1)];
    g_fc6[i] = __uint_as_float(f2tf32(fmaxf(s, 0.0f)));   // tf32-valued (fc7 A side)
}
__global__ void reduce_fc7_kernel(const float* __restrict__ b2) {
    int i = blockIdx.x * blockDim.x + threadIdx.x;
    if (i >= R_ROIS * HID) return;
    float s = 0.0f;
#pragma unroll
    for (int q = 0; q < SPLITS7; q++) s += g_part[(size_t)q * R_ROIS * HID + i];
    s += b2[i & (HID - 1)];
    g_fc7[i] = fmaxf(s, 0.0f);
}

// ============================ heads: split-K mini-GEMM ============================
__global__ void __launch_bounds__(512) heads_gemm_kernel(const float* __restrict__ Wl,
                                                         const float* __restrict__ Ws) {
    __shared__ float As[128 * 33];
    __shared__ float Wt[32 * 106];
    const int s   = blockIdx.x;
    const int k0  = s * 32;
    const int tid = threadIdx.x;

    for (int i = tid; i < 128 * 32; i += 512) {
        int r = i >> 5, k = i & 31;
        As[r * 33 + k] = g_fc7[(size_t)r * HID + k0 + k];
    }
    for (int i = tid; i < 32 * HOUT; i += 512) {
        int k = i / HOUT, n = i % HOUT;
        Wt[k * 106 + n] = (n < NLOC) ? Wl[(size_t)(k0 + k) * NLOC + n]
                                     : Ws[(size_t)(k0 + k) * NSCORE + (n - NLOC)];
    }
    __syncthreads();

    int rg = tid >> 4;
    int ng = tid & 15;
    if (ng < 15) {
        float acc[4][7];
#pragma unroll
        for (int rr = 0; rr < 4; rr++)
#pragma unroll
            for (int jj = 0; jj < 7; jj++) acc[rr][jj] = 0.0f;

        for (int k = 0; k < 32; k++) {
            float w[7], a[4];
#pragma unroll
            for (int jj = 0; jj < 7; jj++) w[jj] = Wt[k * 106 + ng * 7 + jj];
#pragma unroll
            for (int rr = 0; rr < 4; rr++) a[rr] = As[(rg * 4 + rr) * 33 + k];
#pragma unroll
            for (int rr = 0; rr < 4; rr++)
#pragma unroll
                for (int jj = 0; jj < 7; jj++)
                    acc[rr][jj] = fmaf(a[rr], w[jj], acc[rr][jj]);
        }
        float* P = g_part + (size_t)s * (R_ROIS * HOUT);
#pragma unroll
        for (int rr = 0; rr < 4; rr++)
#pragma unroll
            for (int jj = 0; jj < 7; jj++)
                P[(rg * 4 + rr) * HOUT + ng * 7 + jj] = acc[rr][jj];
    }
}

__global__ void heads_reduce_kernel(const float* __restrict__ bl,
                                    const float* __restrict__ bs,
                                    float* __restrict__ out) {
    int i = blockIdx.x * blockDim.x + threadIdx.x;
    if (i >= R_ROIS * HOUT) return;
    int r = i / HOUT, n = i % HOUT;
    float s = 0.0f;
    for (int q = 0; q < HSPLITS; q++) s += g_part[(size_t)q * (R_ROIS * HOUT) + i];
    if (n < NLOC) {
        out[(size_t)r * NLOC + n] = s + bl[n];
    } else {
        out[(size_t)R_ROIS * NLOC + (size_t)r * NSCORE + (n - NLOC)] = s + bs[n - NLOC];
    }
}

// ============================ launch ============================
extern "C" void kernel_launch(void* const* d_in, const int* in_sizes, int n_in,
                              void* d_out, int out_size) {
    const float* x    = (const float*)d_in[0];
    const float* rois = (const float*)d_in[1];
    const int*   idx  = (const int*)  d_in[2];
    const float* W1   = (const float*)d_in[3];
    const float* b1   = (const float*)d_in[4];
    const float* W2   = (const float*)d_in[5];
    const float* b2   = (const float*)d_in[6];
    const float* Wl   = (const float*)d_in[7];
    const float* bl   = (const float*)d_in[8];
    const float* Ws   = (const float*)d_in[9];
    const float* bs   = (const float*)d_in[10];
    float* out = (float*)d_out;

    cudaFuncSetAttribute(gemm_tc_kernel, cudaFuncAttributeMaxDynamicSharedMemorySize, SMEM_TOT);

    // 1) RoI pool -> g_flat [128, 25088] (tf32-valued)
    roi_pool_kernel<<<(R_ROIS * FLATK + 255) / 256, 256>>>(x, rois, idx);

    // 2) fc6: K=25088 -> 392 K64-iters, 9 splits of <=44; grid 16 x 9 = 144 CTAs
    gemm_tc_kernel<<<dim3(HID / 256, SPLITS6), 256, SMEM_TOT>>>(W1, 0, 44);
    reduce_fc6_kernel<<<(R_ROIS * HID + 255) / 256, 256>>>(b1);

    // 3) fc7: K=4096 -> 64 K64-iters, 8 splits of 8; grid 16 x 8 = 128 CTAs
    gemm_tc_kernel<<<dim3(HID / 256, SPLITS7), 256, SMEM_TOT>>>(W2, 1, 8);
    reduce_fc7_kernel<<<(R_ROIS * HID + 255) / 256, 256>>>(b2);

    // 4) heads: 128-split mini-GEMM + reduce -> out = [locs 128*84 | scores 128*21]
    heads_gemm_kernel<<<HSPLITS, 512>>>(Wl, Ws);
    heads_reduce_kernel<<<(R_ROIS * HOUT + 255) / 256, 256>>>(bl, bs, out);
}